// round 7
// baseline (speedup 1.0000x reference)
#include <cuda_runtime.h>

// AdaptiveFilter: per-pixel learned bilateral filter, 2x2 pixel blocking.
// out_c(p) = sum_k x_c(p+dk) * e_k / sum_k e_k,
//   e_k = 2^( w_k*log2e - (S*d_k)^2 ),  S = sqrt(50*log2e),
//   d_k = sum_c |g_c(p+dk)-g_c(p)|  (guidance pre-scaled by S in smem).
// Softmax normalizer cancels in the ratio. Each thread computes a 2x2 pixel
// quad; every shared window cell serves up to 4 pixels (LDS/pixel: 32 instrs,
// 384B). Grid=1024 CTAs at 7 CTAs/SM -> exactly one wave.

namespace {
constexpr int B = 2, C = 3, H = 512, W = 512;
constexpr int BX = 16, BY = 8;        // 128 threads
constexpr int PX = 2, PY = 2;         // 2x2 pixels per thread
constexpr int TW = BX * PX;           // 32
constexpr int TH = BY * PY;           // 16
constexpr int HALO = 3;
constexpr int SW = TW + 2 * HALO;     // 38
constexpr int SH = TH + 2 * HALO;     // 22
constexpr float LOG2E = 1.4426950408889634f;
constexpr float GS = 8.49321796f;     // sqrt(50*log2e)
}

__device__ __forceinline__ float ex2f(float v) {
    float r;
    asm("ex2.approx.f32 %0, %1;" : "=f"(r) : "f"(v));
    return r;
}

__global__ __launch_bounds__(BX * BY, 7)
void adaptive_filter_kernel(const float* __restrict__ x,
                            const float* __restrict__ g,
                            const float* __restrict__ w0,
                            float* __restrict__ out) {
    // Packed shared tiles: sgx = (S*g0, S*g1, S*g2, x0), sx2 = (x1, x2).
    __shared__ float4 sgx[SH][SW + 1];
    __shared__ float2 sx2[SH][SW + 1];

    const int b   = blockIdx.z;
    const int h0  = blockIdx.y * TH;
    const int w0c = blockIdx.x * TW;
    const int tid = threadIdx.y * BX + threadIdx.x;

    const float* __restrict__ gb = g + (size_t)b * C * H * W;
    const float* __restrict__ xb = x + (size_t)b * C * H * W;

    // Cooperative halo load with reflect padding (pad=3 << 512, one reflection).
    for (int idx = tid; idx < SH * SW; idx += BX * BY) {
        const int ty = idx / SW;
        const int tx = idx - ty * SW;
        int gy = h0 + ty - HALO;
        gy = gy < 0 ? -gy : (gy >= H ? 2 * H - 2 - gy : gy);
        int gx = w0c + tx - HALO;
        gx = gx < 0 ? -gx : (gx >= W ? 2 * W - 2 - gx : gx);
        const int p = gy * W + gx;
        sgx[ty][tx] = make_float4(gb[p] * GS, gb[H * W + p] * GS,
                                  gb[2 * H * W + p] * GS, xb[p]);
        sx2[ty][tx] = make_float2(xb[H * W + p], xb[2 * H * W + p]);
    }
    __syncthreads();

    const int px0 = threadIdx.x * PX;     // tile-local col of quad
    const int py0 = threadIdx.y * PY;     // tile-local row of quad
    const int h   = h0 + py0;
    const int w   = w0c + px0;

    // Per-pixel half-kernel logits: 16 floats = 4 float4 rows per pixel.
    // Pixel (pr,pc) base: wb + (pr*W + pc)*4 (float4 units).
    const float4* __restrict__ wb =
        reinterpret_cast<const float4*>(w0) + ((size_t)b * H * W + (size_t)h * W + w) * 4;

    // Center guidance (pre-scaled) per pixel, p = pr*2+pc.
    float cx[4], cy[4], cz[4];
#pragma unroll
    for (int pr = 0; pr < 2; ++pr)
#pragma unroll
        for (int pc = 0; pc < 2; ++pc) {
            const float4 c = sgx[py0 + pr + HALO][px0 + pc + HALO];
            const int p = pr * 2 + pc;
            cx[p] = c.x; cy[p] = c.y; cz[p] = c.z;
        }

    float n0[4] = {0.f, 0.f, 0.f, 0.f}, n1[4] = {0.f, 0.f, 0.f, 0.f},
          n2[4] = {0.f, 0.f, 0.f, 0.f}, dn[4] = {0.f, 0.f, 0.f, 0.f};

#pragma unroll
    for (int i = 0; i < PY + 6; ++i) {        // window rows py0+i
        // Kernel-row logits (scaled by log2 e). Pixel row pr valid iff 0<=i-pr<=6.
        float wl[4][4];
#pragma unroll
        for (int pr = 0; pr < 2; ++pr) {
            const int kr = i - pr;
            if (kr < 0 || kr > 6) continue;
            const int hi = kr < 4 ? kr : 6 - kr;
#pragma unroll
            for (int pc = 0; pc < 2; ++pc) {
                const float4 t = __ldg(wb + ((size_t)pr * W + pc) * 4 + hi);
                const int p = pr * 2 + pc;
                wl[p][0] = t.x * LOG2E; wl[p][1] = t.y * LOG2E;
                wl[p][2] = t.z * LOG2E; wl[p][3] = t.w * LOG2E;
            }
        }

#pragma unroll
        for (int j = 0; j < PX + 6; ++j) {    // window cols px0+j
            // One shared read per cell, consumed by up to 4 pixels.
            const float4 v = sgx[py0 + i][px0 + j];
            const float2 u = sx2[py0 + i][px0 + j];
#pragma unroll
            for (int pr = 0; pr < 2; ++pr) {
                if (i - pr < 0 || i - pr > 6) continue;
#pragma unroll
                for (int pc = 0; pc < 2; ++pc) {
                    const int kc = j - pc;
                    if (kc < 0 || kc > 6) continue;
                    const int hj = kc < 4 ? kc : 6 - kc;
                    const int p = pr * 2 + pc;
                    const float dx = v.x - cx[p];
                    const float dy = v.y - cy[p];
                    const float dz = v.z - cz[p];
                    const float s = fabsf(dx) + fabsf(dy) + fabsf(dz);
                    const float e = ex2f(fmaf(s, -s, wl[p][hj]));
                    n0[p] = fmaf(v.w, e, n0[p]);
                    n1[p] = fmaf(u.x, e, n1[p]);
                    n2[p] = fmaf(u.y, e, n2[p]);
                    dn[p] += e;
                }
            }
        }
    }

    // Stores: adjacent horizontal pixels -> float2 per channel per pixel-row.
    const size_t o = ((size_t)b * C * H + (size_t)h) * W + w;
#pragma unroll
    for (int pr = 0; pr < 2; ++pr) {
        const float ia = __fdividef(1.0f, dn[pr * 2 + 0]);
        const float ib = __fdividef(1.0f, dn[pr * 2 + 1]);
        const size_t orow = o + (size_t)pr * W;
        *reinterpret_cast<float2*>(out + orow) =
            make_float2(n0[pr * 2] * ia, n0[pr * 2 + 1] * ib);
        *reinterpret_cast<float2*>(out + orow + (size_t)H * W) =
            make_float2(n1[pr * 2] * ia, n1[pr * 2 + 1] * ib);
        *reinterpret_cast<float2*>(out + orow + (size_t)2 * H * W) =
            make_float2(n2[pr * 2] * ia, n2[pr * 2 + 1] * ib);
    }
}

extern "C" void kernel_launch(void* const* d_in, const int* in_sizes, int n_in,
                              void* d_out, int out_size) {
    const float* x  = (const float*)d_in[0];
    const float* g  = (const float*)d_in[1];
    const float* w0 = (const float*)d_in[2];
    float* out = (float*)d_out;

    dim3 block(BX, BY);
    dim3 grid(W / TW, H / TH, B);
    adaptive_filter_kernel<<<grid, block>>>(x, g, w0, out);
}

// round 8
// speedup vs baseline: 1.0484x; 1.0484x over previous
#include <cuda_runtime.h>

// AdaptiveFilter: per-pixel learned bilateral filter, PY=4 vertical blocking,
// 64-thread CTAs, 14 CTAs/SM (single wave on 148 SMs).
// out_c(p) = sum_k x_c(p+dk) * e_k / sum_k e_k,
//   e_k = 2^( w_k*log2e - (S*d_k)^2 ),  S = sqrt(50*log2e),
//   d_k = sum_c |g_c(p+dk)-g_c(p)|  (guidance pre-scaled by S in smem).
// Softmax normalizer cancels in the ratio.
// Four vertically adjacent pixels per thread share each shared window cell
// (LDS bytes/pixel: 420 vs 672 for PY=2), lane stride stays 16B (dense,
// conflict-free LDS phases).

namespace {
constexpr int B = 2, C = 3, H = 512, W = 512;
constexpr int BX = 32, BY = 2;       // 64 threads
constexpr int PY = 4;                // pixels per thread (vertical)
constexpr int TW = BX;               // 32
constexpr int TH = BY * PY;          // 8
constexpr int HALO = 3;
constexpr int SW = TW + 2 * HALO;    // 38
constexpr int SH = TH + 2 * HALO;    // 14
constexpr float LOG2E = 1.4426950408889634f;
constexpr float GS = 8.49321796f;    // sqrt(50*log2e)
}

__device__ __forceinline__ float ex2f(float v) {
    float r;
    asm("ex2.approx.f32 %0, %1;" : "=f"(r) : "f"(v));
    return r;
}

__global__ __launch_bounds__(BX * BY, 14)
void adaptive_filter_kernel(const float* __restrict__ x,
                            const float* __restrict__ g,
                            const float* __restrict__ w0,
                            float* __restrict__ out) {
    // Packed shared tiles: sgx = (S*g0, S*g1, S*g2, x0), sx2 = (x1, x2).
    __shared__ float4 sgx[SH][SW + 1];
    __shared__ float2 sx2[SH][SW + 1];

    const int b   = blockIdx.z;
    const int h0  = blockIdx.y * TH;
    const int w0c = blockIdx.x * TW;
    const int tid = threadIdx.y * BX + threadIdx.x;

    const float* __restrict__ gb = g + (size_t)b * C * H * W;
    const float* __restrict__ xb = x + (size_t)b * C * H * W;

    // Cooperative halo load with reflect padding (pad=3 << 512, one reflection).
    for (int idx = tid; idx < SH * SW; idx += BX * BY) {
        const int ty = idx / SW;
        const int tx = idx - ty * SW;
        int gy = h0 + ty - HALO;
        gy = gy < 0 ? -gy : (gy >= H ? 2 * H - 2 - gy : gy);
        int gx = w0c + tx - HALO;
        gx = gx < 0 ? -gx : (gx >= W ? 2 * W - 2 - gx : gx);
        const int p = gy * W + gx;
        sgx[ty][tx] = make_float4(gb[p] * GS, gb[H * W + p] * GS,
                                  gb[2 * H * W + p] * GS, xb[p]);
        sx2[ty][tx] = make_float2(xb[H * W + p], xb[2 * H * W + p]);
    }
    __syncthreads();

    const int tx  = threadIdx.x;
    const int py0 = threadIdx.y * PY;       // tile-local row of pixel 0
    const int h   = h0 + py0;
    const int w   = w0c + tx;

    // Per-pixel half-kernel logits: 16 contiguous floats = 4 float4 rows,
    // reloaded per window-row (rows repeat 0,1,2,3,2,1,0 -> L1 hits).
    const float4* __restrict__ wb =
        reinterpret_cast<const float4*>(w0) + ((size_t)b * H * W + (size_t)h * W + w) * 4;

    // Center guidance (pre-scaled) per pixel.
    float cx[PY], cy[PY], cz[PY];
#pragma unroll
    for (int p = 0; p < PY; ++p) {
        const float4 c = sgx[py0 + p + HALO][tx + HALO];
        cx[p] = c.x; cy[p] = c.y; cz[p] = c.z;
    }

    float n0[PY], n1[PY], n2[PY], dn[PY];
#pragma unroll
    for (int p = 0; p < PY; ++p) { n0[p] = n1[p] = n2[p] = dn[p] = 0.f; }

#pragma unroll
    for (int i = 0; i < PY + 6; ++i) {       // window rows py0+i
        const int row = py0 + i;

        // Kernel-row logits (pre-scaled by log2 e). Pixel p valid iff 0<=i-p<=6.
        float wl[PY][4];
#pragma unroll
        for (int p = 0; p < PY; ++p) {
            const int kr = i - p;
            if (kr < 0 || kr > 6) continue;
            const int hi = kr < 4 ? kr : 6 - kr;
            const float4 t = __ldg(wb + p * (W * 4) + hi);
            wl[p][0] = t.x * LOG2E; wl[p][1] = t.y * LOG2E;
            wl[p][2] = t.z * LOG2E; wl[p][3] = t.w * LOG2E;
        }

#pragma unroll
        for (int j = 0; j < 7; ++j) {
            const int hj = j < 4 ? j : 6 - j;
            // One shared read per (i,j) cell, consumed by all valid pixels.
            const float4 v = sgx[row][tx + j];
            const float2 u = sx2[row][tx + j];
#pragma unroll
            for (int p = 0; p < PY; ++p) {
                if (i - p < 0 || i - p > 6) continue;
                const float s = fabsf(v.x - cx[p]) + fabsf(v.y - cy[p]) +
                                fabsf(v.z - cz[p]);
                const float e = ex2f(fmaf(s, -s, wl[p][hj]));
                n0[p] = fmaf(v.w, e, n0[p]);
                n1[p] = fmaf(u.x, e, n1[p]);
                n2[p] = fmaf(u.y, e, n2[p]);
                dn[p] += e;
            }
        }
    }

    const size_t o0 = ((size_t)b * C * H + (size_t)h) * W + w;
#pragma unroll
    for (int p = 0; p < PY; ++p) {
        const float inv = __fdividef(1.0f, dn[p]);
        const size_t o = o0 + (size_t)p * W;
        out[o]                     = n0[p] * inv;
        out[o + (size_t)H * W]     = n1[p] * inv;
        out[o + (size_t)2 * H * W] = n2[p] * inv;
    }
}

extern "C" void kernel_launch(void* const* d_in, const int* in_sizes, int n_in,
                              void* d_out, int out_size) {
    const float* x  = (const float*)d_in[0];
    const float* g  = (const float*)d_in[1];
    const float* w0 = (const float*)d_in[2];
    float* out = (float*)d_out;

    dim3 block(BX, BY);
    dim3 grid(W / TW, H / TH, B);
    adaptive_filter_kernel<<<grid, block>>>(x, g, w0, out);
}

// round 9
// speedup vs baseline: 1.1341x; 1.0817x over previous
#include <cuda_runtime.h>

// AdaptiveFilter: per-pixel learned bilateral filter.
// PY=2 vertical blocking (R4 structure) + guidance pre-scale (1-FFMA exp arg)
// + 64-thread CTAs at 16 CTAs/SM for finer wave granularity.
// out_c(p) = sum_k x_c(p+dk) * e_k / sum_k e_k,
//   e_k = 2^( w_k*log2e - (S*d_k)^2 ),  S = sqrt(50*log2e),
//   d_k = sum_c |g_c(p+dk)-g_c(p)|  (guidance pre-scaled by S in smem).
// Softmax normalizer cancels in the ratio.

namespace {
constexpr int B = 2, C = 3, H = 512, W = 512;
constexpr int BX = 16, BY = 4;       // 64 threads
constexpr int PY = 2;                // pixels per thread (vertical)
constexpr int TW = BX;               // 16
constexpr int TH = BY * PY;          // 8
constexpr int HALO = 3;
constexpr int SW = TW + 2 * HALO;    // 22
constexpr int SH = TH + 2 * HALO;    // 14
constexpr float LOG2E = 1.4426950408889634f;
constexpr float GS = 8.49321796f;    // sqrt(50*log2e)
}

__device__ __forceinline__ float ex2f(float v) {
    float r;
    asm("ex2.approx.f32 %0, %1;" : "=f"(r) : "f"(v));
    return r;
}

__global__ __launch_bounds__(BX * BY, 16)
void adaptive_filter_kernel(const float* __restrict__ x,
                            const float* __restrict__ g,
                            const float* __restrict__ w0,
                            float* __restrict__ out) {
    // Packed shared tiles: sgx = (S*g0, S*g1, S*g2, x0), sx2 = (x1, x2).
    __shared__ float4 sgx[SH][SW + 1];
    __shared__ float2 sx2[SH][SW + 1];

    const int b   = blockIdx.z;
    const int h0  = blockIdx.y * TH;
    const int w0c = blockIdx.x * TW;
    const int tid = threadIdx.y * BX + threadIdx.x;

    const float* __restrict__ gb = g + (size_t)b * C * H * W;
    const float* __restrict__ xb = x + (size_t)b * C * H * W;

    // Cooperative halo load with reflect padding (pad=3 << 512, one reflection).
    for (int idx = tid; idx < SH * SW; idx += BX * BY) {
        const int ty = idx / SW;
        const int tx = idx - ty * SW;
        int gy = h0 + ty - HALO;
        gy = gy < 0 ? -gy : (gy >= H ? 2 * H - 2 - gy : gy);
        int gx = w0c + tx - HALO;
        gx = gx < 0 ? -gx : (gx >= W ? 2 * W - 2 - gx : gx);
        const int p = gy * W + gx;
        sgx[ty][tx] = make_float4(gb[p] * GS, gb[H * W + p] * GS,
                                  gb[2 * H * W + p] * GS, xb[p]);
        sx2[ty][tx] = make_float2(xb[H * W + p], xb[2 * H * W + p]);
    }
    __syncthreads();

    const int tx  = threadIdx.x;
    const int py0 = threadIdx.y * PY;       // tile-local row of pixel 0
    const int h   = h0 + py0;
    const int w   = w0c + tx;

    // Per-pixel half-kernel logits: 16 contiguous floats = 4 float4 rows,
    // loaded per window-row; identical addresses across reflected rows are
    // CSE'd by the compiler (__ldg + restrict), so each row loads once.
    const float4* __restrict__ wb0 =
        reinterpret_cast<const float4*>(w0) + ((size_t)b * H * W + (size_t)h * W + w) * 4;
    const float4* __restrict__ wb1 = wb0 + (size_t)W * 4;

    // Center guidance (pre-scaled) per pixel.
    const float4 cc0 = sgx[py0 + HALO][tx + HALO];
    const float4 cc1 = sgx[py0 + 1 + HALO][tx + HALO];

    float n0[PY] = {0.f, 0.f}, n1[PY] = {0.f, 0.f},
          n2[PY] = {0.f, 0.f}, dn[PY] = {0.f, 0.f};

#pragma unroll
    for (int i = 0; i < 8; ++i) {            // window rows py0+i
        const int row = py0 + i;

        // Kernel-row logits (pre-scaled by log2 e); compile-time predication.
        float wl0[4], wl1[4];
        if (i <= 6) {                        // pixel 0: kernel row i
            const int hi = i < 4 ? i : 6 - i;
            const float4 t = __ldg(&wb0[hi]);
            wl0[0] = t.x * LOG2E; wl0[1] = t.y * LOG2E;
            wl0[2] = t.z * LOG2E; wl0[3] = t.w * LOG2E;
        }
        if (i >= 1) {                        // pixel 1: kernel row i-1
            const int kr = i - 1;
            const int hi = kr < 4 ? kr : 6 - kr;
            const float4 t = __ldg(&wb1[hi]);
            wl1[0] = t.x * LOG2E; wl1[1] = t.y * LOG2E;
            wl1[2] = t.z * LOG2E; wl1[3] = t.w * LOG2E;
        }

#pragma unroll
        for (int j = 0; j < 7; ++j) {
            const int hj = j < 4 ? j : 6 - j;
            // One shared read per (i,j) cell, consumed by both pixels.
            const float4 v = sgx[row][tx + j];
            const float2 u = sx2[row][tx + j];
            if (i <= 6) {
                const float s = fabsf(v.x - cc0.x) + fabsf(v.y - cc0.y) +
                                fabsf(v.z - cc0.z);
                const float e = ex2f(fmaf(s, -s, wl0[hj]));
                n0[0] = fmaf(v.w, e, n0[0]);
                n1[0] = fmaf(u.x, e, n1[0]);
                n2[0] = fmaf(u.y, e, n2[0]);
                dn[0] += e;
            }
            if (i >= 1) {
                const float s = fabsf(v.x - cc1.x) + fabsf(v.y - cc1.y) +
                                fabsf(v.z - cc1.z);
                const float e = ex2f(fmaf(s, -s, wl1[hj]));
                n0[1] = fmaf(v.w, e, n0[1]);
                n1[1] = fmaf(u.x, e, n1[1]);
                n2[1] = fmaf(u.y, e, n2[1]);
                dn[1] += e;
            }
        }
    }

    const float i0 = __fdividef(1.0f, dn[0]);
    const float i1 = __fdividef(1.0f, dn[1]);

    const size_t o = ((size_t)b * C * H + (size_t)h) * W + w;
    out[o]                         = n0[0] * i0;
    out[o + (size_t)H * W]         = n1[0] * i0;
    out[o + (size_t)2 * H * W]     = n2[0] * i0;
    out[o + W]                     = n0[1] * i1;
    out[o + W + (size_t)H * W]     = n1[1] * i1;
    out[o + W + (size_t)2 * H * W] = n2[1] * i1;
}

extern "C" void kernel_launch(void* const* d_in, const int* in_sizes, int n_in,
                              void* d_out, int out_size) {
    const float* x  = (const float*)d_in[0];
    const float* g  = (const float*)d_in[1];
    const float* w0 = (const float*)d_in[2];
    float* out = (float*)d_out;

    dim3 block(BX, BY);
    dim3 grid(W / TW, H / TH, B);
    adaptive_filter_kernel<<<grid, block>>>(x, g, w0, out);
}

// round 10
// speedup vs baseline: 1.2215x; 1.0770x over previous
#include <cuda_runtime.h>

// AdaptiveFilter: per-pixel learned bilateral filter.
// R4 geometry (16x16 tile, 128 threads, PY=2 vertical blocking) +
// GS-prescaled guidance (1-FFMA exp argument) +
// all 16 per-pixel logits preloaded & prescaled once (registers).
// out_c(p) = sum_k x_c(p+dk) * e_k / sum_k e_k,
//   e_k = 2^( w_k*log2e - (S*d_k)^2 ),  S = sqrt(50*log2e),
//   d_k = sum_c |g_c(p+dk)-g_c(p)|.   Softmax normalizer cancels.

namespace {
constexpr int B = 2, C = 3, H = 512, W = 512;
constexpr int BX = 16, BY = 8;       // 128 threads
constexpr int PY = 2;                // pixels per thread (vertical)
constexpr int TW = BX;               // 16
constexpr int TH = BY * PY;          // 16
constexpr int HALO = 3;
constexpr int SW = TW + 2 * HALO;    // 22
constexpr int SH = TH + 2 * HALO;    // 22
constexpr float LOG2E = 1.4426950408889634f;
constexpr float GS = 8.49321796f;    // sqrt(50*log2e)
}

__device__ __forceinline__ float ex2f(float v) {
    float r;
    asm("ex2.approx.f32 %0, %1;" : "=f"(r) : "f"(v));
    return r;
}

__global__ __launch_bounds__(BX * BY, 7)
void adaptive_filter_kernel(const float* __restrict__ x,
                            const float* __restrict__ g,
                            const float* __restrict__ w0,
                            float* __restrict__ out) {
    // Packed shared tiles: sgx = (S*g0, S*g1, S*g2, x0), sx2 = (x1, x2).
    __shared__ float4 sgx[SH][SW + 1];
    __shared__ float2 sx2[SH][SW + 1];

    const int b   = blockIdx.z;
    const int h0  = blockIdx.y * TH;
    const int w0c = blockIdx.x * TW;
    const int tid = threadIdx.y * BX + threadIdx.x;

    const float* __restrict__ gb = g + (size_t)b * C * H * W;
    const float* __restrict__ xb = x + (size_t)b * C * H * W;

    // Cooperative halo load with reflect padding (pad=3 << 512, one reflection).
    for (int idx = tid; idx < SH * SW; idx += BX * BY) {
        const int ty = idx / SW;
        const int tx = idx - ty * SW;
        int gy = h0 + ty - HALO;
        gy = gy < 0 ? -gy : (gy >= H ? 2 * H - 2 - gy : gy);
        int gx = w0c + tx - HALO;
        gx = gx < 0 ? -gx : (gx >= W ? 2 * W - 2 - gx : gx);
        const int p = gy * W + gx;
        sgx[ty][tx] = make_float4(gb[p] * GS, gb[H * W + p] * GS,
                                  gb[2 * H * W + p] * GS, xb[p]);
        sx2[ty][tx] = make_float2(xb[H * W + p], xb[2 * H * W + p]);
    }

    const int tx  = threadIdx.x;
    const int py0 = threadIdx.y * PY;       // tile-local row of pixel 0
    const int h   = h0 + py0;
    const int w   = w0c + tx;

    // Preload both pixels' 16 half-kernel logits once; prescale by log2 e.
    // (Overlaps with the halo fill before the barrier.)
    const float4* __restrict__ wb0 =
        reinterpret_cast<const float4*>(w0) + ((size_t)b * H * W + (size_t)h * W + w) * 4;
    const float4* __restrict__ wb1 = wb0 + (size_t)W * 4;

    float wl0[4][4], wl1[4][4];
#pragma unroll
    for (int r = 0; r < 4; ++r) {
        const float4 t0 = __ldg(&wb0[r]);
        wl0[r][0] = t0.x * LOG2E; wl0[r][1] = t0.y * LOG2E;
        wl0[r][2] = t0.z * LOG2E; wl0[r][3] = t0.w * LOG2E;
        const float4 t1 = __ldg(&wb1[r]);
        wl1[r][0] = t1.x * LOG2E; wl1[r][1] = t1.y * LOG2E;
        wl1[r][2] = t1.z * LOG2E; wl1[r][3] = t1.w * LOG2E;
    }

    __syncthreads();

    // Center guidance (pre-scaled) per pixel.
    const float4 cc0 = sgx[py0 + HALO][tx + HALO];
    const float4 cc1 = sgx[py0 + 1 + HALO][tx + HALO];

    float n0[PY] = {0.f, 0.f}, n1[PY] = {0.f, 0.f},
          n2[PY] = {0.f, 0.f}, dn[PY] = {0.f, 0.f};

#pragma unroll
    for (int i = 0; i < 8; ++i) {            // window rows py0+i
        const int row = py0 + i;
        const int hi0 = i < 4 ? i : 6 - i;           // pixel 0 logit row (i<=6)
        const int kr1 = i - 1;
        const int hi1 = kr1 < 4 ? kr1 : 6 - kr1;     // pixel 1 logit row (i>=1)

#pragma unroll
        for (int j = 0; j < 7; ++j) {
            const int hj = j < 4 ? j : 6 - j;
            // One shared read per (i,j) cell, consumed by both pixels.
            const float4 v = sgx[row][tx + j];
            const float2 u = sx2[row][tx + j];
            if (i <= 6) {
                const float s = fabsf(v.x - cc0.x) + fabsf(v.y - cc0.y) +
                                fabsf(v.z - cc0.z);
                const float e = ex2f(fmaf(s, -s, wl0[hi0][hj]));
                n0[0] = fmaf(v.w, e, n0[0]);
                n1[0] = fmaf(u.x, e, n1[0]);
                n2[0] = fmaf(u.y, e, n2[0]);
                dn[0] += e;
            }
            if (i >= 1) {
                const float s = fabsf(v.x - cc1.x) + fabsf(v.y - cc1.y) +
                                fabsf(v.z - cc1.z);
                const float e = ex2f(fmaf(s, -s, wl1[hi1][hj]));
                n0[1] = fmaf(v.w, e, n0[1]);
                n1[1] = fmaf(u.x, e, n1[1]);
                n2[1] = fmaf(u.y, e, n2[1]);
                dn[1] += e;
            }
        }
    }

    const float i0 = __fdividef(1.0f, dn[0]);
    const float i1 = __fdividef(1.0f, dn[1]);

    const size_t o = ((size_t)b * C * H + (size_t)h) * W + w;
    out[o]                         = n0[0] * i0;
    out[o + (size_t)H * W]         = n1[0] * i0;
    out[o + (size_t)2 * H * W]     = n2[0] * i0;
    out[o + W]                     = n0[1] * i1;
    out[o + W + (size_t)H * W]     = n1[1] * i1;
    out[o + W + (size_t)2 * H * W] = n2[1] * i1;
}

extern "C" void kernel_launch(void* const* d_in, const int* in_sizes, int n_in,
                              void* d_out, int out_size) {
    const float* x  = (const float*)d_in[0];
    const float* g  = (const float*)d_in[1];
    const float* w0 = (const float*)d_in[2];
    float* out = (float*)d_out;

    dim3 block(BX, BY);
    dim3 grid(W / TW, H / TH, B);
    adaptive_filter_kernel<<<grid, block>>>(x, g, w0, out);
}